// round 2
// baseline (speedup 1.0000x reference)
#include <cuda_runtime.h>
#include <math.h>

// Problem constants (fixed by the reference setup_inputs)
#define NB   4096
#define NH   200
#define DD   128
#define HALF 64
#define HID  64

constexpr int THREADS       = 256;
constexpr int WARPS         = 8;
constexpr int ROWS_PER_WARP = NH / WARPS;  // 25
constexpr int TM            = 5;           // rows per register tile
constexpr int GROUPS        = ROWS_PER_WARP / TM;  // 5

// Shared memory layout (floats):
//   W1s  : DD*HID          = 8192
//   ts   : DD              = 128
//   tile : WARPS*TM*DD     = 5120
//   red  : 2*WARPS         = 16
constexpr int SM_W1   = 0;
constexpr int SM_TS   = SM_W1 + DD * HID;
constexpr int SM_TILE = SM_TS + DD;
constexpr int SM_RED  = SM_TILE + WARPS * TM * DD;
constexpr int SM_FLOATS = SM_RED + 2 * WARPS;
constexpr int SMEM_BYTES = SM_FLOATS * 4;  // 53,856 B

__global__ __launch_bounds__(THREADS, 1)
void nais_region_kernel(
    const int*   __restrict__ history,      // [B, H]
    const int*   __restrict__ target,       // [B]
    const int*   __restrict__ hregion,      // [B, H]
    const int*   __restrict__ tregion,      // [B]
    const float* __restrict__ W_hist,       // [ITEM, 64]
    const float* __restrict__ W_tgt,        // [ITEM, 64]
    const float* __restrict__ W_reg,        // [REGION, 64]
    const float* __restrict__ W1,           // [128, 64]
    const float* __restrict__ b1,           // [64]
    const float* __restrict__ W2,           // [64]
    float*       __restrict__ out)          // [B]
{
    extern __shared__ float sm[];
    float* W1s  = sm + SM_W1;
    float* ts   = sm + SM_TS;
    float* tile = sm + SM_TILE;
    float* red  = sm + SM_RED;

    const int b    = blockIdx.x;
    const int tid  = threadIdx.x;
    const int w    = tid >> 5;
    const int lane = tid & 31;

    const int tb  = target[b];
    const int trb = tregion[b];

    // Stage W1 into smem (vectorized, cooperative)
    {
        const float4* src = reinterpret_cast<const float4*>(W1);
        float4*       dst = reinterpret_cast<float4*>(W1s);
        #pragma unroll
        for (int i = tid; i < DD * HID / 4; i += THREADS) dst[i] = src[i];
    }
    // Stage t = concat(W_tgt[tb], W_reg[trb])
    if (tid < DD) {
        ts[tid] = (tid < HALF) ? W_tgt[(size_t)tb * HALF + tid]
                               : W_reg[(size_t)trb * HALF + (tid - HALF)];
    }
    __syncthreads();

    // Per-lane column constants (lane owns columns c0, c0+1)
    const int   c0  = 2 * lane;
    const float w2a = W2[c0],  w2b = W2[c0 + 1];
    const float bb0 = b1[c0],  bb1 = b1[c0 + 1];

    float S = 0.f, P = 0.f;
    float* mytile = tile + w * (TM * DD);

    for (int g = 0; g < GROUPS; g++) {
        const int row0 = w * ROWS_PER_WARP + g * TM;
        float rowsum[TM];
        int   msk[TM];

        // ---- gather: inp = h * t  (store to per-warp smem tile, compute rowsum) ----
        #pragma unroll
        for (int r = 0; r < TM; r++) {
            const int row  = row0 + r;
            const int hidx = history[b * NH + row];
            const int ridx = hregion[b * NH + row];
            msk[r] = (hidx != tb);
            const float* src = (lane < 16)
                ? (W_hist + (size_t)hidx * HALF + lane * 4)
                : (W_reg  + (size_t)ridx * HALF + (lane - 16) * 4);
            float4 v  = *reinterpret_cast<const float4*>(src);
            float4 tv = *reinterpret_cast<const float4*>(&ts[lane * 4]);
            v.x *= tv.x; v.y *= tv.y; v.z *= tv.z; v.w *= tv.w;
            *reinterpret_cast<float4*>(&mytile[r * DD + lane * 4]) = v;
            float rs = v.x + v.y + v.z + v.w;
            #pragma unroll
            for (int o = 16; o; o >>= 1) rs += __shfl_xor_sync(0xffffffffu, rs, o);
            rowsum[r] = rs;
        }
        __syncwarp();

        // ---- GEMM tile: r1[r][c] = sum_d inp[r][d] * W1[d][c] ----
        float acc0[TM], acc1[TM];
        #pragma unroll
        for (int r = 0; r < TM; r++) { acc0[r] = 0.f; acc1[r] = 0.f; }

        #pragma unroll 8
        for (int d = 0; d < DD; d += 2) {
            const float2 wa = *reinterpret_cast<const float2*>(&W1s[d       * HID + c0]);
            const float2 wb = *reinterpret_cast<const float2*>(&W1s[(d + 1) * HID + c0]);
            #pragma unroll
            for (int r = 0; r < TM; r++) {
                const float2 hp = *reinterpret_cast<const float2*>(&mytile[r * DD + d]);
                acc0[r] = fmaf(hp.x, wa.x, acc0[r]);
                acc1[r] = fmaf(hp.x, wa.y, acc1[r]);
                acc0[r] = fmaf(hp.y, wb.x, acc0[r]);
                acc1[r] = fmaf(hp.y, wb.y, acc1[r]);
            }
        }

        // ---- epilogue: relu -> dot W2 -> masked exp -> accumulate S, P ----
        #pragma unroll
        for (int r = 0; r < TM; r++) {
            float v0 = fmaxf(acc0[r] + bb0, 0.f);
            float v1 = fmaxf(acc1[r] + bb1, 0.f);
            float p  = v0 * w2a + v1 * w2b;
            #pragma unroll
            for (int o = 16; o; o >>= 1) p += __shfl_xor_sync(0xffffffffu, p, o);
            const float e = msk[r] ? expf(p) : 0.f;
            S += e;
            P += e * rowsum[r];
        }
        __syncwarp();  // tile reuse next group
    }

    // ---- block reduction + beta-softmax + pred + sigmoid ----
    if (lane == 0) { red[w] = S; red[WARPS + w] = P; }
    __syncthreads();
    if (tid == 0) {
        float St = 0.f, Pt = 0.f;
        #pragma unroll
        for (int i = 0; i < WARPS; i++) { St += red[i]; Pt += red[WARPS + i]; }
        const float pred = Pt / sqrtf(St);   // BETA = 0.5 -> exp_sum^0.5
        out[b] = 1.f / (1.f + expf(-pred));
    }
}

extern "C" void kernel_launch(void* const* d_in, const int* in_sizes, int n_in,
                              void* d_out, int out_size)
{
    const int*   history = (const int*)  d_in[0];
    const int*   target  = (const int*)  d_in[1];
    const int*   hregion = (const int*)  d_in[2];
    const int*   tregion = (const int*)  d_in[3];
    const float* W_hist  = (const float*)d_in[4];
    const float* W_tgt   = (const float*)d_in[5];
    const float* W_reg   = (const float*)d_in[6];
    const float* W1      = (const float*)d_in[7];
    const float* b1      = (const float*)d_in[8];
    const float* W2      = (const float*)d_in[9];
    float*       out     = (float*)d_out;

    (void)in_sizes; (void)n_in; (void)out_size;

    cudaFuncSetAttribute(nais_region_kernel,
                         cudaFuncAttributeMaxDynamicSharedMemorySize, SMEM_BYTES);

    nais_region_kernel<<<NB, THREADS, SMEM_BYTES>>>(
        history, target, hregion, tregion,
        W_hist, W_tgt, W_reg, W1, b1, W2, out);
}

// round 3
// speedup vs baseline: 1.0015x; 1.0015x over previous
#include <cuda_runtime.h>
#include <math.h>

// Problem constants (fixed by the reference setup_inputs)
#define NB   4096
#define NH   200
#define DD   128
#define HALF 64
#define HID  64

constexpr int THREADS       = 256;
constexpr int WARPS         = 8;
constexpr int ROWS_PER_WARP = NH / WARPS;  // 25
constexpr int TM            = 5;           // rows per register tile
constexpr int GROUPS        = ROWS_PER_WARP / TM;  // 5

// Shared memory layout (floats):
//   W1s  : DD*HID          = 8192
//   ts   : DD              = 128
//   tile : WARPS*TM*DD     = 5120
//   red  : 2*WARPS         = 16
constexpr int SM_W1   = 0;
constexpr int SM_TS   = SM_W1 + DD * HID;
constexpr int SM_TILE = SM_TS + DD;
constexpr int SM_RED  = SM_TILE + WARPS * TM * DD;
constexpr int SM_FLOATS = SM_RED + 2 * WARPS;
constexpr int SMEM_BYTES = SM_FLOATS * 4;  // 53,856 B

__global__ __launch_bounds__(THREADS, 1)
void nais_region_kernel(
    const int*   __restrict__ history,      // [B, H]
    const int*   __restrict__ target,       // [B]
    const int*   __restrict__ hregion,      // [B, H]
    const int*   __restrict__ tregion,      // [B]
    const float* __restrict__ W_hist,       // [ITEM, 64]
    const float* __restrict__ W_tgt,        // [ITEM, 64]
    const float* __restrict__ W_reg,        // [REGION, 64]
    const float* __restrict__ W1,           // [128, 64]
    const float* __restrict__ b1,           // [64]
    const float* __restrict__ W2,           // [64]
    float*       __restrict__ out)          // [B]
{
    extern __shared__ float sm[];
    float* W1s  = sm + SM_W1;
    float* ts   = sm + SM_TS;
    float* tile = sm + SM_TILE;
    float* red  = sm + SM_RED;

    const int b    = blockIdx.x;
    const int tid  = threadIdx.x;
    const int w    = tid >> 5;
    const int lane = tid & 31;

    const int tb  = target[b];
    const int trb = tregion[b];

    // Stage W1 into smem (vectorized, cooperative)
    {
        const float4* src = reinterpret_cast<const float4*>(W1);
        float4*       dst = reinterpret_cast<float4*>(W1s);
        #pragma unroll
        for (int i = tid; i < DD * HID / 4; i += THREADS) dst[i] = src[i];
    }
    // Stage t = concat(W_tgt[tb], W_reg[trb])
    if (tid < DD) {
        ts[tid] = (tid < HALF) ? W_tgt[(size_t)tb * HALF + tid]
                               : W_reg[(size_t)trb * HALF + (tid - HALF)];
    }
    __syncthreads();

    // Per-lane column constants (lane owns columns c0, c0+1)
    const int   c0  = 2 * lane;
    const float w2a = W2[c0],  w2b = W2[c0 + 1];
    const float bb0 = b1[c0],  bb1 = b1[c0 + 1];

    float S = 0.f, P = 0.f;
    float* mytile = tile + w * (TM * DD);

    for (int g = 0; g < GROUPS; g++) {
        const int row0 = w * ROWS_PER_WARP + g * TM;
        float rowsum[TM];
        int   msk[TM];

        // ---- gather: inp = h * t  (store to per-warp smem tile, compute rowsum) ----
        #pragma unroll
        for (int r = 0; r < TM; r++) {
            const int row  = row0 + r;
            const int hidx = history[b * NH + row];
            const int ridx = hregion[b * NH + row];
            msk[r] = (hidx != tb);
            const float* src = (lane < 16)
                ? (W_hist + (size_t)hidx * HALF + lane * 4)
                : (W_reg  + (size_t)ridx * HALF + (lane - 16) * 4);
            float4 v  = *reinterpret_cast<const float4*>(src);
            float4 tv = *reinterpret_cast<const float4*>(&ts[lane * 4]);
            v.x *= tv.x; v.y *= tv.y; v.z *= tv.z; v.w *= tv.w;
            *reinterpret_cast<float4*>(&mytile[r * DD + lane * 4]) = v;
            float rs = v.x + v.y + v.z + v.w;
            #pragma unroll
            for (int o = 16; o; o >>= 1) rs += __shfl_xor_sync(0xffffffffu, rs, o);
            rowsum[r] = rs;
        }
        __syncwarp();

        // ---- GEMM tile: r1[r][c] = sum_d inp[r][d] * W1[d][c] ----
        float acc0[TM], acc1[TM];
        #pragma unroll
        for (int r = 0; r < TM; r++) { acc0[r] = 0.f; acc1[r] = 0.f; }

        #pragma unroll 8
        for (int d = 0; d < DD; d += 2) {
            const float2 wa = *reinterpret_cast<const float2*>(&W1s[d       * HID + c0]);
            const float2 wb = *reinterpret_cast<const float2*>(&W1s[(d + 1) * HID + c0]);
            #pragma unroll
            for (int r = 0; r < TM; r++) {
                const float2 hp = *reinterpret_cast<const float2*>(&mytile[r * DD + d]);
                acc0[r] = fmaf(hp.x, wa.x, acc0[r]);
                acc1[r] = fmaf(hp.x, wa.y, acc1[r]);
                acc0[r] = fmaf(hp.y, wb.x, acc0[r]);
                acc1[r] = fmaf(hp.y, wb.y, acc1[r]);
            }
        }

        // ---- epilogue: relu -> dot W2 -> masked exp -> accumulate S, P ----
        #pragma unroll
        for (int r = 0; r < TM; r++) {
            float v0 = fmaxf(acc0[r] + bb0, 0.f);
            float v1 = fmaxf(acc1[r] + bb1, 0.f);
            float p  = v0 * w2a + v1 * w2b;
            #pragma unroll
            for (int o = 16; o; o >>= 1) p += __shfl_xor_sync(0xffffffffu, p, o);
            const float e = msk[r] ? expf(p) : 0.f;
            S += e;
            P += e * rowsum[r];
        }
        __syncwarp();  // tile reuse next group
    }

    // ---- block reduction + beta-softmax + pred + sigmoid ----
    if (lane == 0) { red[w] = S; red[WARPS + w] = P; }
    __syncthreads();
    if (tid == 0) {
        float St = 0.f, Pt = 0.f;
        #pragma unroll
        for (int i = 0; i < WARPS; i++) { St += red[i]; Pt += red[WARPS + i]; }
        const float pred = Pt / sqrtf(St);   // BETA = 0.5 -> exp_sum^0.5
        out[b] = 1.f / (1.f + expf(-pred));
    }
}

extern "C" void kernel_launch(void* const* d_in, const int* in_sizes, int n_in,
                              void* d_out, int out_size)
{
    const int*   history = (const int*)  d_in[0];
    const int*   target  = (const int*)  d_in[1];
    const int*   hregion = (const int*)  d_in[2];
    const int*   tregion = (const int*)  d_in[3];
    const float* W_hist  = (const float*)d_in[4];
    const float* W_tgt   = (const float*)d_in[5];
    const float* W_reg   = (const float*)d_in[6];
    const float* W1      = (const float*)d_in[7];
    const float* b1      = (const float*)d_in[8];
    const float* W2      = (const float*)d_in[9];
    float*       out     = (float*)d_out;

    (void)in_sizes; (void)n_in; (void)out_size;

    cudaFuncSetAttribute(nais_region_kernel,
                         cudaFuncAttributeMaxDynamicSharedMemorySize, SMEM_BYTES);

    nais_region_kernel<<<NB, THREADS, SMEM_BYTES>>>(
        history, target, hregion, tregion,
        W_hist, W_tgt, W_reg, W1, b1, W2, out);
}